// round 1
// baseline (speedup 1.0000x reference)
#include <cuda_runtime.h>
#include <cuda_bf16.h>

// ============================================================================
// Compile-time reproduction of np.random.RandomState(0) op sequence
// ============================================================================
struct OpT { int kind; int a; int b; };   // kind: 0=rx 1=ry 2=rz 3=cnot
struct MTc { unsigned mt[624]; int mti; };

constexpr unsigned mt_next(MTc &s) {
    if (s.mti >= 624) {
        for (int i = 0; i < 624; ++i) {
            unsigned y = (s.mt[i] & 0x80000000u) | (s.mt[(i + 1) % 624] & 0x7fffffffu);
            unsigned v = s.mt[(i + 397) % 624] ^ (y >> 1);
            if (y & 1u) v ^= 0x9908b0dfu;
            s.mt[i] = v;
        }
        s.mti = 0;
    }
    unsigned y = s.mt[s.mti++];
    y ^= y >> 11;
    y ^= (y << 7)  & 0x9d2c5680u;
    y ^= (y << 15) & 0xefc60000u;
    y ^= y >> 18;
    return y;
}
// numpy legacy rk_interval: inclusive max, masked rejection on 32-bit draws
constexpr unsigned mt_interval(MTc &s, unsigned maxv) {
    unsigned mask = maxv;
    mask |= mask >> 1; mask |= mask >> 2; mask |= mask >> 4;
    mask |= mask >> 8; mask |= mask >> 16;
    unsigned v = mt_next(s) & mask;
    while (v > maxv) v = mt_next(s) & mask;
    return v;
}
struct Ops { OpT ops[20]; };
constexpr Ops make_ops() {
    Ops o{};
    MTc s{};
    s.mt[0] = 0u;
    for (int i = 1; i < 624; ++i)
        s.mt[i] = 1812433253u * (s.mt[i - 1] ^ (s.mt[i - 1] >> 30)) + (unsigned)i;
    s.mti = 624;
    for (int i = 0; i < 20; ++i) {
        unsigned k = mt_interval(s, 3u);          // randint(4)
        if (k == 3u) {                            // cnot: choice(8,2,replace=False) = permutation(8)[:2]
            int perm[8] = {0,1,2,3,4,5,6,7};
            for (int j = 7; j >= 1; --j) {        // Fisher-Yates, numpy shuffle order
                unsigned x = mt_interval(s, (unsigned)j);
                int t = perm[j]; perm[j] = perm[x]; perm[x] = t;
            }
            o.ops[i] = OpT{3, perm[0], perm[1]};
        } else {
            unsigned w = mt_interval(s, 7u);      // randint(8)
            o.ops[i] = OpT{(int)k, (int)w, 0};
        }
    }
    return o;
}
constexpr Ops OPS = make_ops();

// ============================================================================
// Device globals (scratch; no runtime allocation allowed)
// ============================================================================
#define MAX_ROWS 16384
__device__ float g_coef[56];                 // 20 ops * (c,s) + 8 final ry * (c,s)
__device__ float g_H[(size_t)MAX_ROWS * 64]; // hidden layer output

// ============================================================================
// Gate application (warp-per-row; lane holds amps i = lane*8 + r)
// wire w <-> index bit p = 7-w ; p<3: register bit ; p>=3: lane bit (p-3)
// ============================================================================
template<int KIND, int A, int B>
__device__ __forceinline__ void gate(float (&re)[8], float (&im)[8], int lane,
                                     float cc, float ss) {
    constexpr unsigned FULL = 0xffffffffu;
    if constexpr (KIND == 3) {                       // CNOT: control A, target B
        constexpr int pc = 7 - A, pt = 7 - B;
        if constexpr (pc < 3 && pt < 3) {            // both register bits: swap
            constexpr int mt = 1 << pt;
            #pragma unroll
            for (int r = 0; r < 8; ++r) {
                if (((r >> pc) & 1) && !((r >> pt) & 1)) {
                    float t0 = re[r]; re[r] = re[r + mt]; re[r + mt] = t0;
                    float t1 = im[r]; im[r] = im[r + mt]; im[r + mt] = t1;
                }
            }
        } else if constexpr (pc < 3 && pt >= 3) {    // ctrl reg bit, tgt lane bit
            constexpr int ml = 1 << (pt - 3);
            #pragma unroll
            for (int r = 0; r < 8; ++r) {
                if ((r >> pc) & 1) {
                    re[r] = __shfl_xor_sync(FULL, re[r], ml);
                    im[r] = __shfl_xor_sync(FULL, im[r], ml);
                }
            }
        } else if constexpr (pc >= 3 && pt < 3) {    // ctrl lane bit, tgt reg bit
            constexpr int mt = 1 << pt;
            bool bc = (lane >> (pc - 3)) & 1;
            #pragma unroll
            for (int r = 0; r < 8; ++r) {
                if (!((r >> pt) & 1)) {
                    float a0 = re[r], a1 = re[r + mt];
                    re[r] = bc ? a1 : a0; re[r + mt] = bc ? a0 : a1;
                    float b0 = im[r], b1v = im[r + mt];
                    im[r] = bc ? b1v : b0; im[r + mt] = bc ? b0 : b1v;
                }
            }
        } else {                                     // both lane bits
            int bc = (lane >> (pc - 3)) & 1;
            int src = lane ^ (bc << (pt - 3));
            #pragma unroll
            for (int r = 0; r < 8; ++r) {
                re[r] = __shfl_sync(FULL, re[r], src);
                im[r] = __shfl_sync(FULL, im[r], src);
            }
        }
    } else if constexpr (KIND == 2) {                // RZ on wire A
        constexpr int p = 7 - A;
        if constexpr (p < 3) {
            #pragma unroll
            for (int r = 0; r < 8; ++r) {
                float se = ((r >> p) & 1) ? ss : -ss;
                float a = re[r], b = im[r];
                re[r] = cc * a - se * b;
                im[r] = cc * b + se * a;
            }
        } else {
            float se = ((lane >> (p - 3)) & 1) ? ss : -ss;
            #pragma unroll
            for (int r = 0; r < 8; ++r) {
                float a = re[r], b = im[r];
                re[r] = cc * a - se * b;
                im[r] = cc * b + se * a;
            }
        }
    } else if constexpr (KIND == 0) {                // RX on wire A
        constexpr int p = 7 - A;
        if constexpr (p < 3) {
            constexpr int m = 1 << p;
            #pragma unroll
            for (int r = 0; r < 8; ++r) {
                if (!((r >> p) & 1)) {
                    int q = r + m;
                    float ar = re[r], ai = im[r], br = re[q], bi = im[q];
                    re[r] = cc * ar + ss * bi; im[r] = cc * ai - ss * br;
                    re[q] = cc * br + ss * ai; im[q] = cc * bi - ss * ar;
                }
            }
        } else {
            constexpr int m = 1 << (p - 3);
            #pragma unroll
            for (int r = 0; r < 8; ++r) {
                float pr = __shfl_xor_sync(FULL, re[r], m);
                float pi = __shfl_xor_sync(FULL, im[r], m);
                float a = re[r], b = im[r];
                re[r] = cc * a + ss * pi;
                im[r] = cc * b - ss * pr;
            }
        }
    } else {                                         // RY on wire A
        constexpr int p = 7 - A;
        if constexpr (p < 3) {
            constexpr int m = 1 << p;
            #pragma unroll
            for (int r = 0; r < 8; ++r) {
                if (!((r >> p) & 1)) {
                    int q = r + m;
                    float ar = re[r], ai = im[r], br = re[q], bi = im[q];
                    re[r] = cc * ar - ss * br; im[r] = cc * ai - ss * bi;
                    re[q] = ss * ar + cc * br; im[q] = ss * ai + cc * bi;
                }
            }
        } else {
            constexpr int m = 1 << (p - 3);
            float sgn = ((lane >> (p - 3)) & 1) ? ss : -ss;
            #pragma unroll
            for (int r = 0; r < 8; ++r) {
                float pr = __shfl_xor_sync(FULL, re[r], m);
                float pi = __shfl_xor_sync(FULL, im[r], m);
                re[r] = cc * re[r] + sgn * pr;
                im[r] = cc * im[r] + sgn * pi;
            }
        }
    }
}

template<int I>
__device__ __forceinline__ void apply_op(float (&re)[8], float (&im)[8], int lane,
                                         const float* cs) {
    gate<OPS.ops[I].kind, OPS.ops[I].a, OPS.ops[I].b>(re, im, lane, cs[2 * I], cs[2 * I + 1]);
}

// ============================================================================
// Kernel 0: coefficient precompute (cos/sin of half-angles)
// ============================================================================
__global__ void coef_kernel(const float* __restrict__ rp, const float* __restrict__ ryt) {
    int t = threadIdx.x;
    if (t < 20) {
        float a = rp[t] * 0.5f;
        g_coef[2 * t]     = cosf(a);
        g_coef[2 * t + 1] = sinf(a);
    } else if (t < 28) {
        int w = t - 20;
        float a = ryt[w] * 0.5f;
        g_coef[40 + 2 * w] = cosf(a);
        g_coef[41 + 2 * w] = sinf(a);
    }
}

// ============================================================================
// Kernel 1: warp-per-row statevector sim + layer 1 (8 -> 64, relu) -> g_H
// ============================================================================
__global__ __launch_bounds__(256)
void sim_kernel(const float* __restrict__ x, const float* __restrict__ W1,
                const float* __restrict__ b1, int rows) {
    __shared__ float cs[56];
    if (threadIdx.x < 56) cs[threadIdx.x] = g_coef[threadIdx.x];
    __syncthreads();

    int gw   = (int)((blockIdx.x * blockDim.x + threadIdx.x) >> 5);
    int lane = threadIdx.x & 31;
    if (gw >= rows) return;

    const float* f = x + (size_t)gw * 512;
    float c[8], s[8];
    #pragma unroll
    for (int w = 0; w < 8; ++w) {
        float v = __ldg(f + w) * 0.5f;
        __sincosf(v, &s[w], &c[w]);
    }

    // product-state init: amp(i) = prod_w (bit ? sin : cos), bit of wire w at index bit 7-w
    float lf = 1.0f;
    #pragma unroll
    for (int w = 0; w < 5; ++w) lf *= ((lane >> (4 - w)) & 1) ? s[w] : c[w];
    float re[8], im[8];
    #pragma unroll
    for (int r = 0; r < 8; ++r) {
        float v = lf;
        v *= (r & 4) ? s[5] : c[5];
        v *= (r & 2) ? s[6] : c[6];
        v *= (r & 1) ? s[7] : c[7];
        re[r] = v; im[r] = 0.0f;
    }

    // 20 random ops (compile-time sequence)
    apply_op<0>(re, im, lane, cs);   apply_op<1>(re, im, lane, cs);
    apply_op<2>(re, im, lane, cs);   apply_op<3>(re, im, lane, cs);
    apply_op<4>(re, im, lane, cs);   apply_op<5>(re, im, lane, cs);
    apply_op<6>(re, im, lane, cs);   apply_op<7>(re, im, lane, cs);
    apply_op<8>(re, im, lane, cs);   apply_op<9>(re, im, lane, cs);
    apply_op<10>(re, im, lane, cs);  apply_op<11>(re, im, lane, cs);
    apply_op<12>(re, im, lane, cs);  apply_op<13>(re, im, lane, cs);
    apply_op<14>(re, im, lane, cs);  apply_op<15>(re, im, lane, cs);
    apply_op<16>(re, im, lane, cs);  apply_op<17>(re, im, lane, cs);
    apply_op<18>(re, im, lane, cs);  apply_op<19>(re, im, lane, cs);

    // final RY layer (wires 0..7, runtime angles)
    gate<1, 0, 0>(re, im, lane, cs[40], cs[41]);
    gate<1, 1, 0>(re, im, lane, cs[42], cs[43]);
    gate<1, 2, 0>(re, im, lane, cs[44], cs[45]);
    gate<1, 3, 0>(re, im, lane, cs[46], cs[47]);
    gate<1, 4, 0>(re, im, lane, cs[48], cs[49]);
    gate<1, 5, 0>(re, im, lane, cs[50], cs[51]);
    gate<1, 6, 0>(re, im, lane, cs[52], cs[53]);
    gate<1, 7, 0>(re, im, lane, cs[54], cs[55]);

    // probabilities and Z expectations
    float p[8];
    #pragma unroll
    for (int r = 0; r < 8; ++r) p[r] = re[r] * re[r] + im[r] * im[r];
    float ptot = 0.0f;
    #pragma unroll
    for (int r = 0; r < 8; ++r) ptot += p[r];

    float ev[8];
    ev[0] = ((lane >> 4) & 1) ? -ptot : ptot;
    ev[1] = ((lane >> 3) & 1) ? -ptot : ptot;
    ev[2] = ((lane >> 2) & 1) ? -ptot : ptot;
    ev[3] = ((lane >> 1) & 1) ? -ptot : ptot;
    ev[4] = ((lane >> 0) & 1) ? -ptot : ptot;
    float e5 = 0.0f, e6 = 0.0f, e7 = 0.0f;
    #pragma unroll
    for (int r = 0; r < 8; ++r) {
        e5 += (r & 4) ? -p[r] : p[r];
        e6 += (r & 2) ? -p[r] : p[r];
        e7 += (r & 1) ? -p[r] : p[r];
    }
    ev[5] = e5; ev[6] = e6; ev[7] = e7;

    #pragma unroll
    for (int off = 16; off > 0; off >>= 1) {
        #pragma unroll
        for (int w = 0; w < 8; ++w)
            ev[w] += __shfl_xor_sync(0xffffffffu, ev[w], off);
    }

    // layer 1: h = relu(ev @ W1^T + b1), each lane computes h[lane], h[lane+32]
    float h0 = __ldg(b1 + lane);
    float h1 = __ldg(b1 + lane + 32);
    #pragma unroll
    for (int w = 0; w < 8; ++w) {
        h0 = fmaf(__ldg(W1 + lane * 8 + w), ev[w], h0);
        h1 = fmaf(__ldg(W1 + (lane + 32) * 8 + w), ev[w], h1);
    }
    h0 = fmaxf(h0, 0.0f);
    h1 = fmaxf(h1, 0.0f);
    g_H[(size_t)gw * 64 + lane]      = h0;
    g_H[(size_t)gw * 64 + 32 + lane] = h1;
}

// ============================================================================
// Kernel 2: out = H @ W2^T + b2   (M x 512, K = 64), fp32 FFMA GEMM
// 128x128 block tile, 8x8 micro-tile, k-major smem with pad 129
// ============================================================================
#define GPAD 129
__global__ __launch_bounds__(256)
void gemm_kernel(const float* __restrict__ W2, const float* __restrict__ b2,
                 float* __restrict__ out) {
    extern __shared__ float smf[];
    float* As = smf;               // [64][129]  H tile  (k-major)
    float* Bs = smf + 64 * GPAD;   // [64][129]  W2 tile (k-major)

    int t  = threadIdx.x;
    int bm = blockIdx.y * 128;
    int bn = blockIdx.x * 128;

    #pragma unroll
    for (int i = 0; i < 32; ++i) {           // 8192 elements per tile / 256 threads
        int idx = i * 256 + t;
        int m = idx >> 6, k = idx & 63;
        As[k * GPAD + m] = g_H[(size_t)(bm + m) * 64 + k];
        Bs[k * GPAD + m] = __ldg(W2 + (size_t)(bn + m) * 64 + k);
    }
    __syncthreads();

    int tx = t & 15, ty = t >> 4;
    float acc[8][8] = {};
    #pragma unroll 8
    for (int k = 0; k < 64; ++k) {
        float a[8], b[8];
        #pragma unroll
        for (int i = 0; i < 8; ++i) a[i] = As[k * GPAD + ty * 8 + i];
        #pragma unroll
        for (int j = 0; j < 8; ++j) b[j] = Bs[k * GPAD + tx + 16 * j];
        #pragma unroll
        for (int i = 0; i < 8; ++i)
            #pragma unroll
            for (int j = 0; j < 8; ++j)
                acc[i][j] = fmaf(a[i], b[j], acc[i][j]);
    }

    #pragma unroll
    for (int j = 0; j < 8; ++j) {
        float bias = __ldg(b2 + bn + tx + 16 * j);
        #pragma unroll
        for (int i = 0; i < 8; ++i)
            out[(size_t)(bm + ty * 8 + i) * 512 + bn + tx + 16 * j] = acc[i][j] + bias;
    }
}

// ============================================================================
// Launch
// ============================================================================
extern "C" void kernel_launch(void* const* d_in, const int* in_sizes, int n_in,
                              void* d_out, int out_size) {
    const float* x   = (const float*)d_in[0];
    const float* ryt = (const float*)d_in[1];
    const float* rp  = (const float*)d_in[2];
    const float* W1  = (const float*)d_in[3];
    const float* b1  = (const float*)d_in[4];
    const float* W2  = (const float*)d_in[5];
    const float* b2  = (const float*)d_in[6];
    float* out = (float*)d_out;

    int rows = in_sizes[0] / 512;            // B*S = 16384

    coef_kernel<<<1, 32>>>(rp, ryt);

    int simBlocks = (rows + 7) / 8;          // 8 warps (rows) per 256-thread block
    sim_kernel<<<simBlocks, 256>>>(x, W1, b1, rows);

    static int smem_set = 0;
    const int gemm_smem = 2 * 64 * GPAD * (int)sizeof(float);
    if (!smem_set) {
        cudaFuncSetAttribute(gemm_kernel, cudaFuncAttributeMaxDynamicSharedMemorySize, gemm_smem);
        smem_set = 1;
    }
    dim3 ggrid(512 / 128, rows / 128);
    gemm_kernel<<<ggrid, 256, gemm_smem>>>(W2, b2, out);
}

// round 2
// speedup vs baseline: 1.4183x; 1.4183x over previous
#include <cuda_runtime.h>
#include <cuda_bf16.h>
#include <cstdint>

// ============================================================================
// Compile-time reproduction of np.random.RandomState(0) op sequence
// ============================================================================
struct OpT { int kind; int a; int b; };   // kind: 0=rx 1=ry 2=rz 3=cnot
struct MTc { unsigned mt[624]; int mti; };

constexpr unsigned mt_next(MTc &s) {
    if (s.mti >= 624) {
        for (int i = 0; i < 624; ++i) {
            unsigned y = (s.mt[i] & 0x80000000u) | (s.mt[(i + 1) % 624] & 0x7fffffffu);
            unsigned v = s.mt[(i + 397) % 624] ^ (y >> 1);
            if (y & 1u) v ^= 0x9908b0dfu;
            s.mt[i] = v;
        }
        s.mti = 0;
    }
    unsigned y = s.mt[s.mti++];
    y ^= y >> 11;
    y ^= (y << 7)  & 0x9d2c5680u;
    y ^= (y << 15) & 0xefc60000u;
    y ^= y >> 18;
    return y;
}
constexpr unsigned mt_interval(MTc &s, unsigned maxv) {
    unsigned mask = maxv;
    mask |= mask >> 1; mask |= mask >> 2; mask |= mask >> 4;
    mask |= mask >> 8; mask |= mask >> 16;
    unsigned v = mt_next(s) & mask;
    while (v > maxv) v = mt_next(s) & mask;
    return v;
}
struct Ops { OpT ops[20]; };
constexpr Ops make_ops() {
    Ops o{};
    MTc s{};
    s.mt[0] = 0u;
    for (int i = 1; i < 624; ++i)
        s.mt[i] = 1812433253u * (s.mt[i - 1] ^ (s.mt[i - 1] >> 30)) + (unsigned)i;
    s.mti = 624;
    for (int i = 0; i < 20; ++i) {
        unsigned k = mt_interval(s, 3u);
        if (k == 3u) {
            int perm[8] = {0,1,2,3,4,5,6,7};
            for (int j = 7; j >= 1; --j) {
                unsigned x = mt_interval(s, (unsigned)j);
                int t = perm[j]; perm[j] = perm[x]; perm[x] = t;
            }
            o.ops[i] = OpT{3, perm[0], perm[1]};
        } else {
            unsigned w = mt_interval(s, 7u);
            o.ops[i] = OpT{(int)k, (int)w, 0};
        }
    }
    return o;
}
constexpr Ops OPS = make_ops();

// ============================================================================
// Device globals (scratch; no runtime allocation allowed)
// ============================================================================
#define MAX_ROWS 16384
__device__ float g_H[(size_t)MAX_ROWS * 64]; // hidden layer output

// ============================================================================
// Gate application (warp-per-row; lane holds amps i = lane*8 + r)
// wire w <-> index bit p = 7-w ; p<3: register bit ; p>=3: lane bit (p-3)
// ============================================================================
template<int KIND, int A, int B>
__device__ __forceinline__ void gate(float (&re)[8], float (&im)[8], int lane,
                                     float cc, float ss) {
    constexpr unsigned FULL = 0xffffffffu;
    if constexpr (KIND == 3) {                       // CNOT: control A, target B
        constexpr int pc = 7 - A, pt = 7 - B;
        if constexpr (pc < 3 && pt < 3) {
            constexpr int mt = 1 << pt;
            #pragma unroll
            for (int r = 0; r < 8; ++r) {
                if (((r >> pc) & 1) && !((r >> pt) & 1)) {
                    float t0 = re[r]; re[r] = re[r + mt]; re[r + mt] = t0;
                    float t1 = im[r]; im[r] = im[r + mt]; im[r + mt] = t1;
                }
            }
        } else if constexpr (pc < 3 && pt >= 3) {
            constexpr int ml = 1 << (pt - 3);
            #pragma unroll
            for (int r = 0; r < 8; ++r) {
                if ((r >> pc) & 1) {
                    re[r] = __shfl_xor_sync(FULL, re[r], ml);
                    im[r] = __shfl_xor_sync(FULL, im[r], ml);
                }
            }
        } else if constexpr (pc >= 3 && pt < 3) {
            constexpr int mt = 1 << pt;
            bool bc = (lane >> (pc - 3)) & 1;
            #pragma unroll
            for (int r = 0; r < 8; ++r) {
                if (!((r >> pt) & 1)) {
                    float a0 = re[r], a1 = re[r + mt];
                    re[r] = bc ? a1 : a0; re[r + mt] = bc ? a0 : a1;
                    float b0 = im[r], b1v = im[r + mt];
                    im[r] = bc ? b1v : b0; im[r + mt] = bc ? b0 : b1v;
                }
            }
        } else {
            int bc = (lane >> (pc - 3)) & 1;
            int src = lane ^ (bc << (pt - 3));
            #pragma unroll
            for (int r = 0; r < 8; ++r) {
                re[r] = __shfl_sync(FULL, re[r], src);
                im[r] = __shfl_sync(FULL, im[r], src);
            }
        }
    } else if constexpr (KIND == 2) {                // RZ
        constexpr int p = 7 - A;
        if constexpr (p < 3) {
            #pragma unroll
            for (int r = 0; r < 8; ++r) {
                float se = ((r >> p) & 1) ? ss : -ss;
                float a = re[r], b = im[r];
                re[r] = cc * a - se * b;
                im[r] = cc * b + se * a;
            }
        } else {
            float se = ((lane >> (p - 3)) & 1) ? ss : -ss;
            #pragma unroll
            for (int r = 0; r < 8; ++r) {
                float a = re[r], b = im[r];
                re[r] = cc * a - se * b;
                im[r] = cc * b + se * a;
            }
        }
    } else if constexpr (KIND == 0) {                // RX
        constexpr int p = 7 - A;
        if constexpr (p < 3) {
            constexpr int m = 1 << p;
            #pragma unroll
            for (int r = 0; r < 8; ++r) {
                if (!((r >> p) & 1)) {
                    int q = r + m;
                    float ar = re[r], ai = im[r], br = re[q], bi = im[q];
                    re[r] = cc * ar + ss * bi; im[r] = cc * ai - ss * br;
                    re[q] = cc * br + ss * ai; im[q] = cc * bi - ss * ar;
                }
            }
        } else {
            constexpr int m = 1 << (p - 3);
            #pragma unroll
            for (int r = 0; r < 8; ++r) {
                float pr = __shfl_xor_sync(FULL, re[r], m);
                float pi = __shfl_xor_sync(FULL, im[r], m);
                float a = re[r], b = im[r];
                re[r] = cc * a + ss * pi;
                im[r] = cc * b - ss * pr;
            }
        }
    } else {                                         // RY
        constexpr int p = 7 - A;
        if constexpr (p < 3) {
            constexpr int m = 1 << p;
            #pragma unroll
            for (int r = 0; r < 8; ++r) {
                if (!((r >> p) & 1)) {
                    int q = r + m;
                    float ar = re[r], ai = im[r], br = re[q], bi = im[q];
                    re[r] = cc * ar - ss * br; im[r] = cc * ai - ss * bi;
                    re[q] = ss * ar + cc * br; im[q] = ss * ai + cc * bi;
                }
            }
        } else {
            constexpr int m = 1 << (p - 3);
            float sgn = ((lane >> (p - 3)) & 1) ? ss : -ss;
            #pragma unroll
            for (int r = 0; r < 8; ++r) {
                float pr = __shfl_xor_sync(FULL, re[r], m);
                float pi = __shfl_xor_sync(FULL, im[r], m);
                re[r] = cc * re[r] + sgn * pr;
                im[r] = cc * im[r] + sgn * pi;
            }
        }
    }
}

template<int I>
__device__ __forceinline__ void apply_op(float (&re)[8], float (&im)[8], int lane,
                                         const float* cs) {
    gate<OPS.ops[I].kind, OPS.ops[I].a, OPS.ops[I].b>(re, im, lane, cs[2 * I], cs[2 * I + 1]);
}

// ============================================================================
// Kernel 1: warp-per-row statevector sim + layer 1 (8 -> 64, relu) -> g_H
// Coefficients computed in-block (no separate launch).
// ============================================================================
__global__ __launch_bounds__(256)
void sim_kernel(const float* __restrict__ x, const float* __restrict__ W1,
                const float* __restrict__ b1,
                const float* __restrict__ rp, const float* __restrict__ ryt,
                int rows) {
    __shared__ float cs[56];
    {
        int t = threadIdx.x;
        if (t < 20) {
            float sv, cv; sincosf(__ldg(rp + t) * 0.5f, &sv, &cv);
            cs[2 * t] = cv; cs[2 * t + 1] = sv;
        } else if (t < 28) {
            int w = t - 20;
            float sv, cv; sincosf(__ldg(ryt + w) * 0.5f, &sv, &cv);
            cs[40 + 2 * w] = cv; cs[41 + 2 * w] = sv;
        }
    }
    __syncthreads();

    int gw   = (int)((blockIdx.x * blockDim.x + threadIdx.x) >> 5);
    int lane = threadIdx.x & 31;
    if (gw >= rows) return;

    const float* f = x + (size_t)gw * 512;
    float c[8], s[8];
    #pragma unroll
    for (int w = 0; w < 8; ++w) {
        float v = __ldg(f + w) * 0.5f;
        __sincosf(v, &s[w], &c[w]);
    }

    float lf = 1.0f;
    #pragma unroll
    for (int w = 0; w < 5; ++w) lf *= ((lane >> (4 - w)) & 1) ? s[w] : c[w];
    float re[8], im[8];
    #pragma unroll
    for (int r = 0; r < 8; ++r) {
        float v = lf;
        v *= (r & 4) ? s[5] : c[5];
        v *= (r & 2) ? s[6] : c[6];
        v *= (r & 1) ? s[7] : c[7];
        re[r] = v; im[r] = 0.0f;
    }

    apply_op<0>(re, im, lane, cs);   apply_op<1>(re, im, lane, cs);
    apply_op<2>(re, im, lane, cs);   apply_op<3>(re, im, lane, cs);
    apply_op<4>(re, im, lane, cs);   apply_op<5>(re, im, lane, cs);
    apply_op<6>(re, im, lane, cs);   apply_op<7>(re, im, lane, cs);
    apply_op<8>(re, im, lane, cs);   apply_op<9>(re, im, lane, cs);
    apply_op<10>(re, im, lane, cs);  apply_op<11>(re, im, lane, cs);
    apply_op<12>(re, im, lane, cs);  apply_op<13>(re, im, lane, cs);
    apply_op<14>(re, im, lane, cs);  apply_op<15>(re, im, lane, cs);
    apply_op<16>(re, im, lane, cs);  apply_op<17>(re, im, lane, cs);
    apply_op<18>(re, im, lane, cs);  apply_op<19>(re, im, lane, cs);

    gate<1, 0, 0>(re, im, lane, cs[40], cs[41]);
    gate<1, 1, 0>(re, im, lane, cs[42], cs[43]);
    gate<1, 2, 0>(re, im, lane, cs[44], cs[45]);
    gate<1, 3, 0>(re, im, lane, cs[46], cs[47]);
    gate<1, 4, 0>(re, im, lane, cs[48], cs[49]);
    gate<1, 5, 0>(re, im, lane, cs[50], cs[51]);
    gate<1, 6, 0>(re, im, lane, cs[52], cs[53]);
    gate<1, 7, 0>(re, im, lane, cs[54], cs[55]);

    float p[8];
    #pragma unroll
    for (int r = 0; r < 8; ++r) p[r] = re[r] * re[r] + im[r] * im[r];
    float ptot = 0.0f;
    #pragma unroll
    for (int r = 0; r < 8; ++r) ptot += p[r];

    float ev[8];
    ev[0] = ((lane >> 4) & 1) ? -ptot : ptot;
    ev[1] = ((lane >> 3) & 1) ? -ptot : ptot;
    ev[2] = ((lane >> 2) & 1) ? -ptot : ptot;
    ev[3] = ((lane >> 1) & 1) ? -ptot : ptot;
    ev[4] = ((lane >> 0) & 1) ? -ptot : ptot;
    float e5 = 0.0f, e6 = 0.0f, e7 = 0.0f;
    #pragma unroll
    for (int r = 0; r < 8; ++r) {
        e5 += (r & 4) ? -p[r] : p[r];
        e6 += (r & 2) ? -p[r] : p[r];
        e7 += (r & 1) ? -p[r] : p[r];
    }
    ev[5] = e5; ev[6] = e6; ev[7] = e7;

    #pragma unroll
    for (int off = 16; off > 0; off >>= 1) {
        #pragma unroll
        for (int w = 0; w < 8; ++w)
            ev[w] += __shfl_xor_sync(0xffffffffu, ev[w], off);
    }

    float h0 = __ldg(b1 + lane);
    float h1 = __ldg(b1 + lane + 32);
    #pragma unroll
    for (int w = 0; w < 8; ++w) {
        h0 = fmaf(__ldg(W1 + lane * 8 + w), ev[w], h0);
        h1 = fmaf(__ldg(W1 + (lane + 32) * 8 + w), ev[w], h1);
    }
    h0 = fmaxf(h0, 0.0f);
    h1 = fmaxf(h1, 0.0f);
    g_H[(size_t)gw * 64 + lane]      = h0;
    g_H[(size_t)gw * 64 + 32 + lane] = h1;
}

// ============================================================================
// Kernel 2: out = H @ W2^T + b2   (M=16384, N=512, K=64)
// tf32 mma.sync.m16n8k8 — 128x128 block tile, 8 warps (4x2), warp = 32x64
// Smem [row][K=64 + pad4] (stride 68 floats -> conflict-free fragment loads)
// ============================================================================
#define KS 68   // smem row stride in floats (64 + 4)

__device__ __forceinline__ uint32_t f2tf32(float f) {
    uint32_t r;
    asm("cvt.rna.tf32.f32 %0, %1;" : "=r"(r) : "f"(f));
    return r;
}

__global__ __launch_bounds__(256)
void gemm_kernel(const float* __restrict__ W2, const float* __restrict__ b2,
                 float* __restrict__ out) {
    extern __shared__ uint32_t smu[];
    uint32_t* As = smu;              // [128][KS] tf32 (H tile, row-major [m][k])
    uint32_t* Bs = smu + 128 * KS;   // [128][KS] tf32 (W2 tile, [n][k])

    int t  = threadIdx.x;
    int bm = blockIdx.y * 128;
    int bn = blockIdx.x * 128;

    // fill smem: 128 rows x 64 k each, float4-vectorized, convert to tf32
    const float4* Hg = (const float4*)(g_H + (size_t)bm * 64);
    const float4* Wg = (const float4*)(W2 + (size_t)bn * 64);
    #pragma unroll
    for (int i = 0; i < 8; ++i) {                 // 2048 float4 per tile / 256 thr
        int i4 = i * 256 + t;
        int m  = i4 >> 4;            // 16 float4 per 64-float row
        int kc = (i4 & 15) * 4;
        float4 va = __ldg(Hg + i4);
        float4 vb = __ldg(Wg + i4);
        uint32_t* pa = As + m * KS + kc;
        uint32_t* pb = Bs + m * KS + kc;
        pa[0] = f2tf32(va.x); pa[1] = f2tf32(va.y); pa[2] = f2tf32(va.z); pa[3] = f2tf32(va.w);
        pb[0] = f2tf32(vb.x); pb[1] = f2tf32(vb.y); pb[2] = f2tf32(vb.z); pb[3] = f2tf32(vb.w);
    }
    __syncthreads();

    int lane = t & 31, wid = t >> 5;
    int wm = (wid >> 1) * 32;        // warp m offset (0,32,64,96)
    int wn = (wid & 1) * 64;         // warp n offset (0,64)
    int g  = lane >> 2;              // group id 0..7
    int tg = lane & 3;               // thread-in-group 0..3

    float acc[2][8][4];
    #pragma unroll
    for (int f = 0; f < 2; ++f)
        #pragma unroll
        for (int j = 0; j < 8; ++j)
            #pragma unroll
            for (int q = 0; q < 4; ++q) acc[f][j][q] = 0.0f;

    #pragma unroll
    for (int kk = 0; kk < 8; ++kk) {
        int kb = kk * 8 + tg;
        uint32_t a[2][4];
        #pragma unroll
        for (int f = 0; f < 2; ++f) {
            int row = wm + f * 16 + g;
            a[f][0] = As[row * KS + kb];
            a[f][1] = As[(row + 8) * KS + kb];
            a[f][2] = As[row * KS + kb + 4];
            a[f][3] = As[(row + 8) * KS + kb + 4];
        }
        uint32_t b[8][2];
        #pragma unroll
        for (int j = 0; j < 8; ++j) {
            int col = wn + j * 8 + g;
            b[j][0] = Bs[col * KS + kb];
            b[j][1] = Bs[col * KS + kb + 4];
        }
        #pragma unroll
        for (int f = 0; f < 2; ++f)
            #pragma unroll
            for (int j = 0; j < 8; ++j)
                asm volatile(
                    "mma.sync.aligned.m16n8k8.row.col.f32.tf32.tf32.f32 "
                    "{%0,%1,%2,%3}, {%4,%5,%6,%7}, {%8,%9}, {%0,%1,%2,%3};"
                    : "+f"(acc[f][j][0]), "+f"(acc[f][j][1]),
                      "+f"(acc[f][j][2]), "+f"(acc[f][j][3])
                    : "r"(a[f][0]), "r"(a[f][1]), "r"(a[f][2]), "r"(a[f][3]),
                      "r"(b[j][0]), "r"(b[j][1]));
    }

    // epilogue: + bias, float2 stores
    #pragma unroll
    for (int j = 0; j < 8; ++j) {
        int col = bn + wn + j * 8 + tg * 2;
        float2 bias = __ldg((const float2*)(b2 + col));
        #pragma unroll
        for (int f = 0; f < 2; ++f) {
            int row = bm + wm + f * 16 + g;
            float2 v0 = { acc[f][j][0] + bias.x, acc[f][j][1] + bias.y };
            float2 v1 = { acc[f][j][2] + bias.x, acc[f][j][3] + bias.y };
            *(float2*)(out + (size_t)row * 512 + col)       = v0;
            *(float2*)(out + (size_t)(row + 8) * 512 + col) = v1;
        }
    }
}

// ============================================================================
// Launch
// ============================================================================
extern "C" void kernel_launch(void* const* d_in, const int* in_sizes, int n_in,
                              void* d_out, int out_size) {
    const float* x   = (const float*)d_in[0];
    const float* ryt = (const float*)d_in[1];
    const float* rp  = (const float*)d_in[2];
    const float* W1  = (const float*)d_in[3];
    const float* b1  = (const float*)d_in[4];
    const float* W2  = (const float*)d_in[5];
    const float* b2  = (const float*)d_in[6];
    float* out = (float*)d_out;

    int rows = in_sizes[0] / 512;            // B*S = 16384

    int simBlocks = (rows + 7) / 8;
    sim_kernel<<<simBlocks, 256>>>(x, W1, b1, rp, ryt, rows);

    const int gemm_smem = 2 * 128 * KS * (int)sizeof(uint32_t);   // ~69.6 KB
    cudaFuncSetAttribute(gemm_kernel, cudaFuncAttributeMaxDynamicSharedMemorySize, gemm_smem);
    dim3 ggrid(512 / 128, rows / 128);
    gemm_kernel<<<ggrid, 256, gemm_smem>>>(W2, b2, out);
}

// round 3
// speedup vs baseline: 1.5246x; 1.0749x over previous
#include <cuda_runtime.h>
#include <cuda_bf16.h>
#include <cstdint>

// ============================================================================
// Compile-time reproduction of np.random.RandomState(0) op sequence
// ============================================================================
struct OpT { int kind; int a; int b; };   // kind: 0=rx 1=ry 2=rz 3=cnot
struct MTc { unsigned mt[624]; int mti; };

constexpr unsigned mt_next(MTc &s) {
    if (s.mti >= 624) {
        for (int i = 0; i < 624; ++i) {
            unsigned y = (s.mt[i] & 0x80000000u) | (s.mt[(i + 1) % 624] & 0x7fffffffu);
            unsigned v = s.mt[(i + 397) % 624] ^ (y >> 1);
            if (y & 1u) v ^= 0x9908b0dfu;
            s.mt[i] = v;
        }
        s.mti = 0;
    }
    unsigned y = s.mt[s.mti++];
    y ^= y >> 11;
    y ^= (y << 7)  & 0x9d2c5680u;
    y ^= (y << 15) & 0xefc60000u;
    y ^= y >> 18;
    return y;
}
constexpr unsigned mt_interval(MTc &s, unsigned maxv) {
    unsigned mask = maxv;
    mask |= mask >> 1; mask |= mask >> 2; mask |= mask >> 4;
    mask |= mask >> 8; mask |= mask >> 16;
    unsigned v = mt_next(s) & mask;
    while (v > maxv) v = mt_next(s) & mask;
    return v;
}
struct Ops { OpT ops[20]; };
constexpr Ops make_ops() {
    Ops o{};
    MTc s{};
    s.mt[0] = 0u;
    for (int i = 1; i < 624; ++i)
        s.mt[i] = 1812433253u * (s.mt[i - 1] ^ (s.mt[i - 1] >> 30)) + (unsigned)i;
    s.mti = 624;
    for (int i = 0; i < 20; ++i) {
        unsigned k = mt_interval(s, 3u);
        if (k == 3u) {
            int perm[8] = {0,1,2,3,4,5,6,7};
            for (int j = 7; j >= 1; --j) {
                unsigned x = mt_interval(s, (unsigned)j);
                int t = perm[j]; perm[j] = perm[x]; perm[x] = t;
            }
            o.ops[i] = OpT{3, perm[0], perm[1]};
        } else {
            unsigned w = mt_interval(s, 7u);
            o.ops[i] = OpT{(int)k, (int)w, 0};
        }
    }
    return o;
}
constexpr Ops OPS = make_ops();

// ============================================================================
// Device globals
// ============================================================================
#define MAX_ROWS 16384
__device__ float g_H[(size_t)MAX_ROWS * 64];

// ============================================================================
// Packed fp32x2 helpers (Blackwell f32x2 pipe; PTX-only, ptxas won't auto-fuse)
// ============================================================================
__device__ __forceinline__ float2 f2mul(float2 a, float2 b) {
    float2 d;
    asm("{\n\t"
        ".reg .b64 ra, rb, rd;\n\t"
        "mov.b64 ra, {%2, %3};\n\t"
        "mov.b64 rb, {%4, %5};\n\t"
        "mul.rn.f32x2 rd, ra, rb;\n\t"
        "mov.b64 {%0, %1}, rd;\n\t"
        "}"
        : "=f"(d.x), "=f"(d.y)
        : "f"(a.x), "f"(a.y), "f"(b.x), "f"(b.y));
    return d;
}
__device__ __forceinline__ float2 f2fma(float2 a, float2 b, float2 c) {
    float2 d;
    asm("{\n\t"
        ".reg .b64 ra, rb, rc, rd;\n\t"
        "mov.b64 ra, {%2, %3};\n\t"
        "mov.b64 rb, {%4, %5};\n\t"
        "mov.b64 rc, {%6, %7};\n\t"
        "fma.rn.f32x2 rd, ra, rb, rc;\n\t"
        "mov.b64 {%0, %1}, rd;\n\t"
        "}"
        : "=f"(d.x), "=f"(d.y)
        : "f"(a.x), "f"(a.y), "f"(b.x), "f"(b.y), "f"(c.x), "f"(c.y));
    return d;
}
__device__ __forceinline__ float2 f2add(float2 a, float2 b) {
    float2 d;
    asm("{\n\t"
        ".reg .b64 ra, rb, rd;\n\t"
        "mov.b64 ra, {%2, %3};\n\t"
        "mov.b64 rb, {%4, %5};\n\t"
        "add.rn.f32x2 rd, ra, rb;\n\t"
        "mov.b64 {%0, %1}, rd;\n\t"
        "}"
        : "=f"(d.x), "=f"(d.y)
        : "f"(a.x), "f"(a.y), "f"(b.x), "f"(b.y));
    return d;
}
__device__ __forceinline__ float2 shfl_xor2(float2 v, int m) {
    v.x = __shfl_xor_sync(0xffffffffu, v.x, m);
    v.y = __shfl_xor_sync(0xffffffffu, v.y, m);
    return v;
}

// ============================================================================
// Packed gate application.
// Amp index i = lane*8 + r; r packed as pack k = r>>1, half = r&1 (.x even).
// Bit p of r: p==0 -> half; p in {1,2} -> pack bit p-1; p>=3 -> lane bit p-3.
// ============================================================================
template<int KIND, int A, int B>
__device__ __forceinline__ void gateP(float2 (&RE)[4], float2 (&IM)[4], int lane,
                                      float cc, float ss) {
    constexpr unsigned FULL = 0xffffffffu;
    if constexpr (KIND == 3) {                       // CNOT ctrl A tgt B
        constexpr int pc = 7 - A, pt = 7 - B;
        if constexpr (pc < 3 && pt < 3) {
            if constexpr (pt == 0) {                 // swap halves in packs w/ ctrl set
                constexpr int cb = pc - 1;
                #pragma unroll
                for (int k = 0; k < 4; ++k)
                    if ((k >> cb) & 1) {
                        RE[k] = make_float2(RE[k].y, RE[k].x);
                        IM[k] = make_float2(IM[k].y, IM[k].x);
                    }
            } else if constexpr (pc == 0) {          // odd halves swap across packs
                constexpr int tb = pt - 1, mm = 1 << tb;
                #pragma unroll
                for (int k = 0; k < 4; ++k)
                    if (!((k >> tb) & 1)) {
                        int q = k + mm;
                        float t = RE[k].y; RE[k].y = RE[q].y; RE[q].y = t;
                        t = IM[k].y; IM[k].y = IM[q].y; IM[q].y = t;
                    }
            } else {                                 // pack-level swap
                constexpr int cb = pc - 1, tb = pt - 1, mm = 1 << tb;
                #pragma unroll
                for (int k = 0; k < 4; ++k)
                    if (((k >> cb) & 1) && !((k >> tb) & 1)) {
                        float2 t = RE[k]; RE[k] = RE[k + mm]; RE[k + mm] = t;
                        t = IM[k]; IM[k] = IM[k + mm]; IM[k + mm] = t;
                    }
            }
        } else if constexpr (pc < 3 && pt >= 3) {    // ctrl reg, tgt lane
            constexpr int ml = 1 << (pt - 3);
            if constexpr (pc == 0) {                 // odd halves shuffle
                #pragma unroll
                for (int k = 0; k < 4; ++k) {
                    RE[k].y = __shfl_xor_sync(FULL, RE[k].y, ml);
                    IM[k].y = __shfl_xor_sync(FULL, IM[k].y, ml);
                }
            } else {
                constexpr int cb = pc - 1;
                #pragma unroll
                for (int k = 0; k < 4; ++k)
                    if ((k >> cb) & 1) {
                        RE[k] = shfl_xor2(RE[k], ml);
                        IM[k] = shfl_xor2(IM[k], ml);
                    }
            }
        } else if constexpr (pc >= 3 && pt < 3) {    // ctrl lane, tgt reg
            bool bc = (lane >> (pc - 3)) & 1;
            if constexpr (pt == 0) {
                #pragma unroll
                for (int k = 0; k < 4; ++k) {
                    float2 v = RE[k];
                    RE[k] = bc ? make_float2(v.y, v.x) : v;
                    float2 u = IM[k];
                    IM[k] = bc ? make_float2(u.y, u.x) : u;
                }
            } else {
                constexpr int tb = pt - 1, mm = 1 << tb;
                #pragma unroll
                for (int k = 0; k < 4; ++k)
                    if (!((k >> tb) & 1)) {
                        int q = k + mm;
                        float2 a = RE[k], b2v = RE[q];
                        RE[k] = bc ? b2v : a; RE[q] = bc ? a : b2v;
                        float2 c2 = IM[k], d2 = IM[q];
                        IM[k] = bc ? d2 : c2; IM[q] = bc ? c2 : d2;
                    }
            }
        } else {                                     // both lane bits
            int bc = (lane >> (pc - 3)) & 1;
            int src = lane ^ (bc << (pt - 3));
            #pragma unroll
            for (int k = 0; k < 4; ++k) {
                RE[k].x = __shfl_sync(FULL, RE[k].x, src);
                RE[k].y = __shfl_sync(FULL, RE[k].y, src);
                IM[k].x = __shfl_sync(FULL, IM[k].x, src);
                IM[k].y = __shfl_sync(FULL, IM[k].y, src);
            }
        }
    } else if constexpr (KIND == 2) {                // RZ: re'=c a - se b, im'=c b + se a
        constexpr int p = 7 - A;
        float2 C = make_float2(cc, cc);
        if constexpr (p == 0) {
            float2 SE  = make_float2(-ss,  ss);      // se per half
            float2 NSE = make_float2( ss, -ss);
            #pragma unroll
            for (int k = 0; k < 4; ++k) {
                float2 r0 = f2fma(NSE, IM[k], f2mul(C, RE[k]));
                IM[k] = f2fma(SE, RE[k], f2mul(C, IM[k]));
                RE[k] = r0;
            }
        } else if constexpr (p < 3) {
            constexpr int kb = p - 1;
            float2 SP = make_float2( ss,  ss);
            float2 SN = make_float2(-ss, -ss);
            #pragma unroll
            for (int k = 0; k < 4; ++k) {
                float2 SE  = ((k >> kb) & 1) ? SP : SN;
                float2 NSE = ((k >> kb) & 1) ? SN : SP;
                float2 r0 = f2fma(NSE, IM[k], f2mul(C, RE[k]));
                IM[k] = f2fma(SE, RE[k], f2mul(C, IM[k]));
                RE[k] = r0;
            }
        } else {
            float se = ((lane >> (p - 3)) & 1) ? ss : -ss;
            float2 SE  = make_float2( se,  se);
            float2 NSE = make_float2(-se, -se);
            #pragma unroll
            for (int k = 0; k < 4; ++k) {
                float2 r0 = f2fma(NSE, IM[k], f2mul(C, RE[k]));
                IM[k] = f2fma(SE, RE[k], f2mul(C, IM[k]));
                RE[k] = r0;
            }
        }
    } else if constexpr (KIND == 0) {                // RX
        constexpr int p = 7 - A;
        float2 C  = make_float2(cc, cc);
        float2 S  = make_float2( ss,  ss);
        float2 NS = make_float2(-ss, -ss);
        if constexpr (p == 0) {
            #pragma unroll
            for (int k = 0; k < 4; ++k) {
                float2 isw = make_float2(IM[k].y, IM[k].x);
                float2 rsw = make_float2(RE[k].y, RE[k].x);
                RE[k] = f2fma(S,  isw, f2mul(C, RE[k]));
                IM[k] = f2fma(NS, rsw, f2mul(C, IM[k]));
            }
        } else if constexpr (p < 3) {
            constexpr int kb = p - 1, mm = 1 << kb;
            #pragma unroll
            for (int k = 0; k < 4; ++k)
                if (!((k >> kb) & 1)) {
                    int q = k + mm;
                    float2 rk = RE[k], ik = IM[k], rq = RE[q], iq = IM[q];
                    RE[k] = f2fma(S,  iq, f2mul(C, rk));
                    IM[k] = f2fma(NS, rq, f2mul(C, ik));
                    RE[q] = f2fma(S,  ik, f2mul(C, rq));
                    IM[q] = f2fma(NS, rk, f2mul(C, iq));
                }
        } else {
            constexpr int m = 1 << (p - 3);
            #pragma unroll
            for (int k = 0; k < 4; ++k) {
                float2 pr = shfl_xor2(RE[k], m);
                float2 pi = shfl_xor2(IM[k], m);
                RE[k] = f2fma(S,  pi, f2mul(C, RE[k]));
                IM[k] = f2fma(NS, pr, f2mul(C, IM[k]));
            }
        }
    } else {                                         // RY
        constexpr int p = 7 - A;
        float2 C = make_float2(cc, cc);
        if constexpr (p == 0) {
            float2 MS = make_float2(-ss, ss);
            #pragma unroll
            for (int k = 0; k < 4; ++k) {
                float2 rsw = make_float2(RE[k].y, RE[k].x);
                float2 isw = make_float2(IM[k].y, IM[k].x);
                RE[k] = f2fma(MS, rsw, f2mul(C, RE[k]));
                IM[k] = f2fma(MS, isw, f2mul(C, IM[k]));
            }
        } else if constexpr (p < 3) {
            constexpr int kb = p - 1, mm = 1 << kb;
            float2 S  = make_float2( ss,  ss);
            float2 NS = make_float2(-ss, -ss);
            #pragma unroll
            for (int k = 0; k < 4; ++k)
                if (!((k >> kb) & 1)) {
                    int q = k + mm;
                    float2 rk = RE[k], rq = RE[q];
                    RE[k] = f2fma(NS, rq, f2mul(C, rk));
                    RE[q] = f2fma(S,  rk, f2mul(C, rq));
                    float2 ik = IM[k], iq = IM[q];
                    IM[k] = f2fma(NS, iq, f2mul(C, ik));
                    IM[q] = f2fma(S,  ik, f2mul(C, iq));
                }
        } else {
            constexpr int m = 1 << (p - 3);
            float sg = ((lane >> (p - 3)) & 1) ? ss : -ss;
            float2 SG = make_float2(sg, sg);
            #pragma unroll
            for (int k = 0; k < 4; ++k) {
                float2 pr = shfl_xor2(RE[k], m);
                float2 pi = shfl_xor2(IM[k], m);
                RE[k] = f2fma(SG, pr, f2mul(C, RE[k]));
                IM[k] = f2fma(SG, pi, f2mul(C, IM[k]));
            }
        }
    }
}

template<int I>
__device__ __forceinline__ void apply_opP(float2 (&RE)[4], float2 (&IM)[4], int lane,
                                          const float* cs) {
    gateP<OPS.ops[I].kind, OPS.ops[I].a, OPS.ops[I].b>(RE, IM, lane, cs[2 * I], cs[2 * I + 1]);
}

// ============================================================================
// Kernel 1: warp-per-row statevector sim (f32x2 packed) + layer 1 -> g_H
// ============================================================================
__global__ __launch_bounds__(256)
void sim_kernel(const float* __restrict__ x, const float* __restrict__ W1,
                const float* __restrict__ b1,
                const float* __restrict__ rp, const float* __restrict__ ryt,
                int rows) {
    constexpr unsigned FULL = 0xffffffffu;
    __shared__ float cs[56];
    {
        int t = threadIdx.x;
        if (t < 20) {
            float sv, cv; sincosf(__ldg(rp + t) * 0.5f, &sv, &cv);
            cs[2 * t] = cv; cs[2 * t + 1] = sv;
        } else if (t < 28) {
            int w = t - 20;
            float sv, cv; sincosf(__ldg(ryt + w) * 0.5f, &sv, &cv);
            cs[40 + 2 * w] = cv; cs[41 + 2 * w] = sv;
        }
    }
    __syncthreads();

    int gw   = (int)((blockIdx.x * blockDim.x + threadIdx.x) >> 5);
    int lane = threadIdx.x & 31;
    if (gw >= rows) return;

    // distributed sincos: lane w<8 computes wire w, broadcast via shfl
    float myc = 1.0f, mys = 0.0f;
    if (lane < 8) {
        float v = __ldg(x + (size_t)gw * 512 + lane) * 0.5f;
        __sincosf(v, &mys, &myc);
    }
    float c[8], s[8];
    #pragma unroll
    for (int w = 0; w < 8; ++w) {
        c[w] = __shfl_sync(FULL, myc, w);
        s[w] = __shfl_sync(FULL, mys, w);
    }

    // product-state init
    float lf = 1.0f;
    #pragma unroll
    for (int w = 0; w < 5; ++w) lf *= ((lane >> (4 - w)) & 1) ? s[w] : c[w];
    float2 RE[4], IM[4];
    float2 CS7 = make_float2(c[7], s[7]);
    #pragma unroll
    for (int k = 0; k < 4; ++k) {
        float t = lf * ((k & 2) ? s[5] : c[5]) * ((k & 1) ? s[6] : c[6]);
        RE[k] = f2mul(make_float2(t, t), CS7);
        IM[k] = make_float2(0.0f, 0.0f);
    }

    apply_opP<0>(RE, IM, lane, cs);   apply_opP<1>(RE, IM, lane, cs);
    apply_opP<2>(RE, IM, lane, cs);   apply_opP<3>(RE, IM, lane, cs);
    apply_opP<4>(RE, IM, lane, cs);   apply_opP<5>(RE, IM, lane, cs);
    apply_opP<6>(RE, IM, lane, cs);   apply_opP<7>(RE, IM, lane, cs);
    apply_opP<8>(RE, IM, lane, cs);   apply_opP<9>(RE, IM, lane, cs);
    apply_opP<10>(RE, IM, lane, cs);  apply_opP<11>(RE, IM, lane, cs);
    apply_opP<12>(RE, IM, lane, cs);  apply_opP<13>(RE, IM, lane, cs);
    apply_opP<14>(RE, IM, lane, cs);  apply_opP<15>(RE, IM, lane, cs);
    apply_opP<16>(RE, IM, lane, cs);  apply_opP<17>(RE, IM, lane, cs);
    apply_opP<18>(RE, IM, lane, cs);  apply_opP<19>(RE, IM, lane, cs);

    gateP<1, 0, 0>(RE, IM, lane, cs[40], cs[41]);
    gateP<1, 1, 0>(RE, IM, lane, cs[42], cs[43]);
    gateP<1, 2, 0>(RE, IM, lane, cs[44], cs[45]);
    gateP<1, 3, 0>(RE, IM, lane, cs[46], cs[47]);
    gateP<1, 4, 0>(RE, IM, lane, cs[48], cs[49]);
    gateP<1, 5, 0>(RE, IM, lane, cs[50], cs[51]);
    gateP<1, 6, 0>(RE, IM, lane, cs[52], cs[53]);
    gateP<1, 7, 0>(RE, IM, lane, cs[54], cs[55]);

    // probabilities (packed)
    float2 P[4];
    #pragma unroll
    for (int k = 0; k < 4; ++k)
        P[k] = f2fma(RE[k], RE[k], f2mul(IM[k], IM[k]));

    float2 S01 = f2add(P[0], P[1]);
    float2 S23 = f2add(P[2], P[3]);
    float2 SA  = f2add(S01, S23);
    float ptot = SA.x + SA.y;
    float e7   = SA.x - SA.y;                            // r bit0
    float e5   = (S01.x + S01.y) - (S23.x + S23.y);      // r bit2 (pack bit1)
    float2 D01 = f2add(P[0], make_float2(-P[1].x, -P[1].y));
    float2 D23 = f2add(P[2], make_float2(-P[3].x, -P[3].y));
    float e6   = (D01.x + D01.y) + (D23.x + D23.y);      // r bit1 (pack bit0)

    float2 EA = make_float2(((lane >> 4) & 1) ? -ptot : ptot,
                            ((lane >> 3) & 1) ? -ptot : ptot);
    float2 EB = make_float2(((lane >> 2) & 1) ? -ptot : ptot,
                            ((lane >> 1) & 1) ? -ptot : ptot);
    float2 EC = make_float2(((lane >> 0) & 1) ? -ptot : ptot, e5);
    float2 ED = make_float2(e6, e7);

    #pragma unroll
    for (int off = 16; off > 0; off >>= 1) {
        EA = f2add(EA, shfl_xor2(EA, off));
        EB = f2add(EB, shfl_xor2(EB, off));
        EC = f2add(EC, shfl_xor2(EC, off));
        ED = f2add(ED, shfl_xor2(ED, off));
    }
    float ev[8] = {EA.x, EA.y, EB.x, EB.y, EC.x, EC.y, ED.x, ED.y};

    // layer 1: h = relu(ev @ W1^T + b1)
    const float4* w1a = (const float4*)(W1 + (size_t)lane * 8);
    const float4* w1b = (const float4*)(W1 + (size_t)(lane + 32) * 8);
    float4 a0 = __ldg(w1a), a1 = __ldg(w1a + 1);
    float4 v0 = __ldg(w1b), v1 = __ldg(w1b + 1);
    float h0 = __ldg(b1 + lane);
    float h1 = __ldg(b1 + lane + 32);
    h0 = fmaf(a0.x, ev[0], h0); h0 = fmaf(a0.y, ev[1], h0);
    h0 = fmaf(a0.z, ev[2], h0); h0 = fmaf(a0.w, ev[3], h0);
    h0 = fmaf(a1.x, ev[4], h0); h0 = fmaf(a1.y, ev[5], h0);
    h0 = fmaf(a1.z, ev[6], h0); h0 = fmaf(a1.w, ev[7], h0);
    h1 = fmaf(v0.x, ev[0], h1); h1 = fmaf(v0.y, ev[1], h1);
    h1 = fmaf(v0.z, ev[2], h1); h1 = fmaf(v0.w, ev[3], h1);
    h1 = fmaf(v1.x, ev[4], h1); h1 = fmaf(v1.y, ev[5], h1);
    h1 = fmaf(v1.z, ev[6], h1); h1 = fmaf(v1.w, ev[7], h1);
    h0 = fmaxf(h0, 0.0f);
    h1 = fmaxf(h1, 0.0f);
    g_H[(size_t)gw * 64 + lane]      = h0;
    g_H[(size_t)gw * 64 + 32 + lane] = h1;
}

// ============================================================================
// Kernel 2: out = H @ W2^T + b2  (M=16384, N=512, K=64) tf32 mma.m16n8k8
// Fragment-order smem: uint2(A[row][k], A[row][k+4]) at [row*ST2 + kk*4 + tg]
// ST2=36 -> addr8B mod 16 = 4g+tg : 2-phase conflict-free LDS.64
// ============================================================================
#define ST2 36

__device__ __forceinline__ uint32_t f2tf32(float f) {
    uint32_t r;
    asm("cvt.rna.tf32.f32 %0, %1;" : "=r"(r) : "f"(f));
    return r;
}

__global__ __launch_bounds__(256)
void gemm_kernel(const float* __restrict__ W2, const float* __restrict__ b2,
                 float* __restrict__ out) {
    extern __shared__ uint2 sm2[];
    uint2* As = sm2;                 // 128 * ST2
    uint2* Bs = sm2 + 128 * ST2;

    int t  = threadIdx.x;
    int bm = blockIdx.y * 128;
    int bn = blockIdx.x * 128;

    const float4* Hg = (const float4*)(g_H + (size_t)bm * 64);
    const float4* Wg = (const float4*)(W2 + (size_t)bn * 64);
    #pragma unroll
    for (int i = 0; i < 4; ++i) {               // 1024 (row,kk) tasks / 256 threads
        int task = i * 256 + t;
        int row = task >> 3, kk = task & 7;
        float4 a0 = __ldg(Hg + row * 16 + kk * 2);
        float4 a1 = __ldg(Hg + row * 16 + kk * 2 + 1);
        uint2* pa = As + row * ST2 + kk * 4;
        pa[0] = make_uint2(f2tf32(a0.x), f2tf32(a1.x));
        pa[1] = make_uint2(f2tf32(a0.y), f2tf32(a1.y));
        pa[2] = make_uint2(f2tf32(a0.z), f2tf32(a1.z));
        pa[3] = make_uint2(f2tf32(a0.w), f2tf32(a1.w));
        float4 bb0 = __ldg(Wg + row * 16 + kk * 2);
        float4 bb1 = __ldg(Wg + row * 16 + kk * 2 + 1);
        uint2* pb = Bs + row * ST2 + kk * 4;
        pb[0] = make_uint2(f2tf32(bb0.x), f2tf32(bb1.x));
        pb[1] = make_uint2(f2tf32(bb0.y), f2tf32(bb1.y));
        pb[2] = make_uint2(f2tf32(bb0.z), f2tf32(bb1.z));
        pb[3] = make_uint2(f2tf32(bb0.w), f2tf32(bb1.w));
    }
    __syncthreads();

    int lane = t & 31, wid = t >> 5;
    int wm = (wid >> 1) * 32;        // warp m offset
    int wn = (wid & 1) * 64;         // warp n offset
    int g  = lane >> 2;
    int tg = lane & 3;

    float acc[2][8][4];
    #pragma unroll
    for (int f = 0; f < 2; ++f)
        #pragma unroll
        for (int j = 0; j < 8; ++j)
            #pragma unroll
            for (int q = 0; q < 4; ++q) acc[f][j][q] = 0.0f;

    #pragma unroll
    for (int kk = 0; kk < 8; ++kk) {
        int kb = kk * 4 + tg;
        uint2 va0 = As[(wm + g) * ST2 + kb];
        uint2 va1 = As[(wm + g + 8) * ST2 + kb];
        uint2 va2 = As[(wm + g + 16) * ST2 + kb];
        uint2 va3 = As[(wm + g + 24) * ST2 + kb];
        uint32_t a[2][4] = {
            { va0.x, va1.x, va0.y, va1.y },
            { va2.x, va3.x, va2.y, va3.y }
        };
        uint2 wb[8];
        #pragma unroll
        for (int j = 0; j < 8; ++j)
            wb[j] = Bs[(wn + j * 8 + g) * ST2 + kb];

        #pragma unroll
        for (int f = 0; f < 2; ++f)
            #pragma unroll
            for (int j = 0; j < 8; ++j)
                asm volatile(
                    "mma.sync.aligned.m16n8k8.row.col.f32.tf32.tf32.f32 "
                    "{%0,%1,%2,%3}, {%4,%5,%6,%7}, {%8,%9}, {%0,%1,%2,%3};"
                    : "+f"(acc[f][j][0]), "+f"(acc[f][j][1]),
                      "+f"(acc[f][j][2]), "+f"(acc[f][j][3])
                    : "r"(a[f][0]), "r"(a[f][1]), "r"(a[f][2]), "r"(a[f][3]),
                      "r"(wb[j].x), "r"(wb[j].y));
    }

    #pragma unroll
    for (int j = 0; j < 8; ++j) {
        int col = bn + wn + j * 8 + tg * 2;
        float2 bias = __ldg((const float2*)(b2 + col));
        #pragma unroll
        for (int f = 0; f < 2; ++f) {
            int row = bm + wm + f * 16 + g;
            float2 o0 = { acc[f][j][0] + bias.x, acc[f][j][1] + bias.y };
            float2 o1 = { acc[f][j][2] + bias.x, acc[f][j][3] + bias.y };
            *(float2*)(out + (size_t)row * 512 + col)       = o0;
            *(float2*)(out + (size_t)(row + 8) * 512 + col) = o1;
        }
    }
}

// ============================================================================
// Launch
// ============================================================================
extern "C" void kernel_launch(void* const* d_in, const int* in_sizes, int n_in,
                              void* d_out, int out_size) {
    const float* x   = (const float*)d_in[0];
    const float* ryt = (const float*)d_in[1];
    const float* rp  = (const float*)d_in[2];
    const float* W1  = (const float*)d_in[3];
    const float* b1  = (const float*)d_in[4];
    const float* W2  = (const float*)d_in[5];
    const float* b2  = (const float*)d_in[6];
    float* out = (float*)d_out;

    int rows = in_sizes[0] / 512;            // B*S = 16384

    int simBlocks = (rows + 7) / 8;
    sim_kernel<<<simBlocks, 256>>>(x, W1, b1, rp, ryt, rows);

    const int gemm_smem = 2 * 128 * ST2 * (int)sizeof(uint2);   // 72 KB
    cudaFuncSetAttribute(gemm_kernel, cudaFuncAttributeMaxDynamicSharedMemorySize, gemm_smem);
    dim3 ggrid(512 / 128, rows / 128);
    gemm_kernel<<<ggrid, 256, gemm_smem>>>(W2, b2, out);
}